// round 16
// baseline (speedup 1.0000x reference)
#include <cuda_runtime.h>
#include <cuda_bf16.h>
#include <math.h>

#define NF 64
#define NBATCH 8
#define NDMAX 12288
#define CELLS (NDMAX * NF)
#define PADCELLS (CELLS + 64 * 64)
#define KS 3

__device__ float g_buf[15][CELLS];
__device__ float g_po[KS][CELLS];
__device__ float g_pms[KS][2 * NDMAX];
__device__ __nv_bfloat16 g_bf[6][PADCELLS];   // Qhi Qlo Khi Klo Vhi Vlo
__device__ float g_part[2][256 * 128];        // alternating BN partial buffers
__device__ int   g_seg[64];
__device__ __nv_bfloat16 g_wtb[8 * 8192];     // 8 weight mats, bf16 hi+lo, swizzled

// ---------------------------------------------------------------------------
// Helpers
// ---------------------------------------------------------------------------
__device__ __forceinline__ int SW(int r, int cb) {
    return r * 128 + (cb ^ ((r & 7) << 4));
}
__device__ __forceinline__ unsigned smu32(const void* p) {
    return (unsigned)__cvta_generic_to_shared(p);
}
__device__ __forceinline__ void cpa16(unsigned dst, const void* src) {
    asm volatile("cp.async.ca.shared.global [%0], [%1], 16;" :: "r"(dst), "l"(src) : "memory");
}
#define CP_COMMIT() asm volatile("cp.async.commit_group;" ::: "memory")
#define CP_WAIT1()  asm volatile("cp.async.wait_group 1;" ::: "memory")
#define CP_WAIT0()  asm volatile("cp.async.wait_group 0;" ::: "memory")

__device__ __forceinline__ void ldsm4(unsigned r[4], unsigned a) {
    asm volatile("ldmatrix.sync.aligned.m8n8.x4.shared.b16 {%0,%1,%2,%3}, [%4];"
                 : "=r"(r[0]), "=r"(r[1]), "=r"(r[2]), "=r"(r[3]) : "r"(a));
}
__device__ __forceinline__ void ldsm4t(unsigned r[4], unsigned a) {
    asm volatile("ldmatrix.sync.aligned.m8n8.x4.trans.shared.b16 {%0,%1,%2,%3}, [%4];"
                 : "=r"(r[0]), "=r"(r[1]), "=r"(r[2]), "=r"(r[3]) : "r"(a));
}
__device__ __forceinline__ void mma_bf(float c[4], const unsigned a[4], const unsigned b[2]) {
    asm volatile(
        "mma.sync.aligned.m16n8k16.row.col.f32.bf16.bf16.f32 "
        "{%0,%1,%2,%3}, {%4,%5,%6,%7}, {%8,%9}, {%0,%1,%2,%3};"
        : "+f"(c[0]), "+f"(c[1]), "+f"(c[2]), "+f"(c[3])
        : "r"(a[0]), "r"(a[1]), "r"(a[2]), "r"(a[3]), "r"(b[0]), "r"(b[1]));
}

__device__ __forceinline__ void bf_split(float v, unsigned short& hb, unsigned short& lb) {
    __nv_bfloat16 h = __float2bfloat16(v);
    hb = __bfloat16_as_ushort(h);
    lb = __bfloat16_as_ushort(__float2bfloat16(v - __bfloat162float(h)));
}
__device__ __forceinline__ void bf_split2(float a, float b, unsigned& hw, unsigned& lw) {
    unsigned short ha, la, hb, lb;
    bf_split(a, ha, la);
    bf_split(b, hb, lb);
    hw = (unsigned)ha | ((unsigned)hb << 16);
    lw = (unsigned)la | ((unsigned)lb << 16);
}

// per-column BN coefficients from partial buffer: y = x*A + B
__device__ __forceinline__ void bn_coeff(const float* part, int nblk, int N, int c,
                                         float g, float be, float& A, float& Bc) {
    float s = 0.f, s2 = 0.f;
    for (int b = 0; b < nblk; b++) { s += part[b * 128 + c]; s2 += part[b * 128 + 64 + c]; }
    float mu = s / (float)N;
    float rs = rsqrtf(s2 / (float)N - mu * mu + 1e-4f);
    A = rs * g;
    Bc = be - mu * A;
}

// ---------------------------------------------------------------------------
// Init: blocks 0-7 convert weights to swizzled bf16 hi/lo; block 8 seg prep.
// slots: 0 Wp1, 1 Wc=Wp1@Wq, 2 Wk, 3 Wv, 4 Wt, 5 Wq1, 6 Wk1, 7 Wv1
// ---------------------------------------------------------------------------
__global__ void __launch_bounds__(256) k_init(
    const float* __restrict__ Wp1, const float* __restrict__ Wq,
    const float* __restrict__ Wk,  const float* __restrict__ Wv,
    const float* __restrict__ Wt,  const float* __restrict__ Wq1,
    const float* __restrict__ Wk1, const float* __restrict__ Wv1,
    const int* __restrict__ pad_idx, int nd, int ne, int lq)
{
    int t = threadIdx.x;
    int blk = blockIdx.x;
    if (blk == 8) {
        int w = t >> 5, lane = t & 31;
        if (w < NBATCH) {
            int cnt = 0;
            for (int l = lane; l < lq; l += 32)
                cnt += (pad_idx[w * lq + l] >= 0) ? 1 : 0;
#pragma unroll
            for (int o = 16; o > 0; o >>= 1) cnt += __shfl_xor_sync(0xffffffffu, cnt, o);
            if (lane == 0) {
                int s = pad_idx[w * lq];
                g_seg[(1 + w) * 4 + 0] = s;
                g_seg[(1 + w) * 4 + 1] = cnt;
                g_seg[(1 + w) * 4 + 2] = s;
                g_seg[(1 + w) * 4 + 3] = cnt;
            }
        }
        if (t == 0) { g_seg[0] = 0; g_seg[1] = nd; g_seg[2] = 0; g_seg[3] = ne; }
        return;
    }

    char* dst = (char*)(g_wtb + (size_t)blk * 8192);

    if (blk == 1) {
        __shared__ float s1[4096], s2[4096];
        for (int i = t; i < 4096; i += 256) { s1[i] = Wp1[i]; s2[i] = Wq[i]; }
        __syncthreads();
        int r = t >> 2, c0 = (t & 3) * 16;
        float acc[16];
#pragma unroll
        for (int j = 0; j < 16; j++) acc[j] = 0.f;
        for (int m = 0; m < 64; m++) {
            float a = s1[r * 64 + m];
#pragma unroll
            for (int j = 0; j < 16; j++) acc[j] += a * s2[m * 64 + c0 + j];
        }
#pragma unroll
        for (int j = 0; j < 16; j++) {
            unsigned short hb, lb;
            bf_split(acc[j], hb, lb);
            int off = SW(r, (c0 + j) * 2);
            *(unsigned short*)(dst + off) = hb;
            *(unsigned short*)(dst + 8192 + off) = lb;
        }
        return;
    }

    const float* src = Wp1;
    if (blk == 2) src = Wk;
    else if (blk == 3) src = Wv;
    else if (blk == 4) src = Wt;
    else if (blk == 5) src = Wq1;
    else if (blk == 6) src = Wk1;
    else if (blk == 7) src = Wv1;
    for (int e = t; e < 4096; e += 256) {
        int r = e >> 6, c = e & 63;
        unsigned short hb, lb;
        bf_split(src[e], hb, lb);
        int off = SW(r, c * 2);
        *(unsigned short*)(dst + off) = hb;
        *(unsigned short*)(dst + 8192 + off) = lb;
    }
}

// ---------------------------------------------------------------------------
// Unified tensor-core GEMM (static smem, direct A loads).
// mode 0: A plain; 1: bn(A); 2: bn(X)+Res (writes Aout); 3: split-K merge.
// ---------------------------------------------------------------------------
struct TJob {
    const float* A; const float* Res;
    const float* pO; const float* pMS;
    const __nv_bfloat16* Wbf;
    float* C; float* Aout;
    __nv_bfloat16* hi; __nv_bfloat16* lo;
    const float* bg; const float* bb; const float* sp; int snb;
    float* part; int N; int mode;
};
struct TJobs { TJob j[4]; };

__global__ void __launch_bounds__(256) k_tgemm(TJobs JJ)
{
    TJob J = JJ.j[blockIdx.y];
    int N = J.N;
    int row0 = blockIdx.x * 64;
    if (row0 >= N) return;

    __shared__ char sAh[8192];
    __shared__ char sAl[8192];
    __shared__ char sWb[16384];
    __shared__ float saux[64 * 3];
    __shared__ float sred[2][4][64];
    int t = threadIdx.x;

    {
        const char* ws = (const char*)J.Wbf;
#pragma unroll
        for (int q = 0; q < 4; q++) {
            int ch = t + 256 * q;
            cpa16(smu32(sWb + ch * 16), ws + ch * 16);
        }
    }
    CP_COMMIT();

    if (t < 64) {
        if (J.mode == 1 || J.mode == 2) {
            bn_coeff(J.sp, J.snb, N, t, J.bg[t], J.bb[t], saux[t], saux[64 + t]);
        } else if (J.mode == 3) {
            int gr = row0 + t;
            if (gr < N) {
                float m[KS], s[KS];
#pragma unroll
                for (int i = 0; i < KS; i++) {
                    m[i] = J.pMS[(size_t)i * 2 * NDMAX + gr * 2];
                    s[i] = J.pMS[(size_t)i * 2 * NDMAX + gr * 2 + 1];
                }
                float mx = m[0];
#pragma unroll
                for (int i = 1; i < KS; i++) mx = fmaxf(mx, m[i]);
                float e[KS], denom = 0.f;
#pragma unroll
                for (int i = 0; i < KS; i++) { e[i] = __expf(m[i] - mx); denom += s[i] * e[i]; }
                float inv = 1.f / denom;
#pragma unroll
                for (int i = 0; i < KS; i++) saux[i * 64 + t] = e[i] * inv;
            } else {
#pragma unroll
                for (int i = 0; i < KS; i++) saux[i * 64 + t] = 0.f;
            }
        } else {
            saux[t] = 1.f; saux[64 + t] = 0.f;
        }
    }
    __syncthreads();

    // Build A bf16 hi/lo planes
#pragma unroll
    for (int i = 0; i < 16; i++) {
        int e = t + 256 * i;
        int r = e >> 6, c = e & 63;
        int gr = row0 + r;
        float v = 0.f;
        if (gr < N) {
            if (J.mode == 3) {
#pragma unroll
                for (int k = 0; k < KS; k++)
                    v += J.pO[(size_t)k * CELLS + (size_t)gr * 64 + c] * saux[k * 64 + r];
            } else if (J.mode == 2) {
                v = J.A[(size_t)gr * 64 + c] * saux[c] + saux[64 + c] + J.Res[(size_t)gr * 64 + c];
                J.Aout[(size_t)gr * 64 + c] = v;
            } else {
                v = J.A[(size_t)gr * 64 + c] * saux[c] + saux[64 + c];
            }
        }
        unsigned short hb, lb;
        bf_split(v, hb, lb);
        int off = SW(r, c * 2);
        *(unsigned short*)(sAh + off) = hb;
        *(unsigned short*)(sAl + off) = lb;
    }
    CP_WAIT0();
    __syncthreads();

    int lane = t & 31, w = t >> 5;
    int mi = w & 3, nh = w >> 2;
    float c4[4][4];
#pragma unroll
    for (int nt = 0; nt < 4; nt++)
#pragma unroll
        for (int k = 0; k < 4; k++) c4[nt][k] = 0.f;

    char* wh = sWb;
    char* wl = sWb + 8192;
#pragma unroll
    for (int ch = 0; ch < 4; ch++) {
        unsigned ah[4], al[4];
        {
            int r = mi * 16 + (lane & 7) + ((lane & 8) ? 8 : 0);
            int cb = ch * 32 + ((lane & 16) ? 16 : 0);
            ldsm4(ah, smu32(sAh + SW(r, cb)));
            ldsm4(al, smu32(sAl + SW(r, cb)));
        }
        unsigned b0h[4], b1h[4], b0l[4], b1l[4];
        {
            int r2 = ch * 16 + (lane & 7) + ((lane & 8) ? 8 : 0);
            int cb0 = (nh * 2 + 0) * 32 + ((lane & 16) ? 16 : 0);
            int cb1 = (nh * 2 + 1) * 32 + ((lane & 16) ? 16 : 0);
            ldsm4t(b0h, smu32(wh + SW(r2, cb0)));
            ldsm4t(b1h, smu32(wh + SW(r2, cb1)));
            ldsm4t(b0l, smu32(wl + SW(r2, cb0)));
            ldsm4t(b1l, smu32(wl + SW(r2, cb1)));
        }
        mma_bf(c4[0], ah, &b0h[0]); mma_bf(c4[0], ah, &b0l[0]); mma_bf(c4[0], al, &b0h[0]);
        mma_bf(c4[1], ah, &b0h[2]); mma_bf(c4[1], ah, &b0l[2]); mma_bf(c4[1], al, &b0h[2]);
        mma_bf(c4[2], ah, &b1h[0]); mma_bf(c4[2], ah, &b1l[0]); mma_bf(c4[2], al, &b1h[0]);
        mma_bf(c4[3], ah, &b1h[2]); mma_bf(c4[3], ah, &b1l[2]); mma_bf(c4[3], al, &b1h[2]);
    }
    __syncthreads();

    float* sO = (float*)sAh;
    int quad = lane >> 2, qi = lane & 3;
    int r0 = mi * 16 + quad, r1 = r0 + 8;
#pragma unroll
    for (int nt = 0; nt < 4; nt++) {
        int colb = nh * 32 + nt * 8 + 2 * qi;
        sO[r0 * 64 + colb]     = c4[nt][0];
        sO[r0 * 64 + colb + 1] = c4[nt][1];
        sO[r1 * 64 + colb]     = c4[nt][2];
        sO[r1 * 64 + colb + 1] = c4[nt][3];
    }
    __syncthreads();

    int c = t & 63, rg = t >> 6;
    float s = 0.f, s2 = 0.f;
#pragma unroll
    for (int i = 0; i < 16; i++) {
        int r = rg * 16 + i;
        int gr = row0 + r;
        if (gr < N) {
            float v = sO[r * 64 + c];
            if (J.C) J.C[(size_t)gr * 64 + c] = v;
            if (J.hi) {
                unsigned short hb, lb;
                bf_split(v, hb, lb);
                *(unsigned short*)&J.hi[(size_t)gr * 64 + c] = hb;
                *(unsigned short*)&J.lo[(size_t)gr * 64 + c] = lb;
            }
            s += v; s2 += v * v;
        }
    }
    if (J.part) {
        sred[0][rg][c] = s; sred[1][rg][c] = s2;
        __syncthreads();
        if (t < 64) {
            float ts = sred[0][0][c] + sred[0][1][c] + sred[0][2][c] + sred[0][3][c];
            float t2 = sred[1][0][c] + sred[1][1][c] + sred[1][2][c] + sred[1][3][c];
            J.part[blockIdx.x * 128 + c] = ts;
            J.part[blockIdx.x * 128 + 64 + c] = t2;
        }
    }
}

// ---------------------------------------------------------------------------
// Pipelined scalar rulebook sparse conv; optional input BN+ReLU, optional
// output BN stats.
// ---------------------------------------------------------------------------
#define GC_SMEM ((2 * 4096 + 2 * 64 * 68) * 4)

__global__ void __launch_bounds__(256) k_gconv(
    const float* __restrict__ F, const int* __restrict__ idx, int K,
    const float* __restrict__ W, float* __restrict__ out, int N,
    float* __restrict__ outpart,
    const float* __restrict__ statpart, int snb,
    const float* __restrict__ bg, const float* __restrict__ bb)
{
    extern __shared__ float dsm[];
    float* sW2 = dsm;
    float* sF2 = dsm + 2 * 4096;
    __shared__ int sIdxAll[27 * 64];
    __shared__ float sred[2][16][64];
    __shared__ float sa[64], sb[64];
    int t = threadIdx.x;
    int row0 = blockIdx.x * 64;
    int a = t >> 4, b = t & 15;

    if (bg && t < 64) bn_coeff(statpart, snb, N, t, bg[t], bb[t], sa[t], sb[t]);
    for (int i = t; i < 64 * K; i += 256) {
        int r = i / K, k = i - r * K;
        int gr = row0 + r;
        sIdxAll[k * 64 + r] = (gr < N) ? idx[gr * K + k] : -1;
    }
    __syncthreads();

    int rr = t >> 2, c0 = t & 3;
    {
        char* wd = (char*)sW2;
        const float* ws = W;
#pragma unroll
        for (int q = 0; q < 4; q++) {
            int c = t + 256 * q;
            cpa16(smu32(wd + c * 16), ws + c * 4);
        }
        int j = sIdxAll[rr];
        if (j >= 0) {
            char* fd = (char*)sF2;
#pragma unroll
            for (int q = 0; q < 4; q++)
                cpa16(smu32(fd + rr * 272 + c0 * 64 + q * 16), F + (size_t)j * 64 + c0 * 16 + q * 4);
        }
    }
    CP_COMMIT();

    float4 acc[4];
#pragma unroll
    for (int i = 0; i < 4; i++) acc[i] = make_float4(0.f, 0.f, 0.f, 0.f);

    for (int k = 0; k < K; k++) {
        __syncthreads();
        if (k + 1 < K) {
            int nb = (k + 1) & 1;
            char* wd = (char*)(sW2 + nb * 4096);
            const float* ws = W + (size_t)(k + 1) * 4096;
#pragma unroll
            for (int q = 0; q < 4; q++) {
                int c = t + 256 * q;
                cpa16(smu32(wd + c * 16), ws + c * 4);
            }
            int j = sIdxAll[(k + 1) * 64 + rr];
            if (j >= 0) {
                char* fd = (char*)(sF2 + nb * 4352);
#pragma unroll
                for (int q = 0; q < 4; q++)
                    cpa16(smu32(fd + rr * 272 + c0 * 64 + q * 16), F + (size_t)j * 64 + c0 * 16 + q * 4);
            }
        }
        CP_COMMIT();
        CP_WAIT1();
        __syncthreads();

        int cb = k & 1;
        float* sW = sW2 + cb * 4096;
        float* sF = sF2 + cb * 4352;
        const int* sIdx = sIdxAll + k * 64;

        if (bg) {
            int j = sIdx[rr];
            if (j >= 0) {
#pragma unroll
                for (int q = 0; q < 4; q++) {
                    int c = c0 * 16 + q * 4;
                    float4 v = *reinterpret_cast<float4*>(&sF[rr * 68 + c]);
                    v.x = fmaxf(v.x * sa[c] + sb[c], 0.f);
                    v.y = fmaxf(v.y * sa[c + 1] + sb[c + 1], 0.f);
                    v.z = fmaxf(v.z * sa[c + 2] + sb[c + 2], 0.f);
                    v.w = fmaxf(v.w * sa[c + 3] + sb[c + 3], 0.f);
                    *reinterpret_cast<float4*>(&sF[rr * 68 + c]) = v;
                }
            }
            __syncthreads();
        }

#pragma unroll
        for (int i = 0; i < 4; i++) {
            int r = a + 16 * i;
            if (sIdx[r] >= 0) {
#pragma unroll 8
                for (int m = 0; m < 64; m++) {
                    float av = sF[r * 68 + m];
                    float4 w = *reinterpret_cast<const float4*>(&sW[m * 64 + 4 * b]);
                    acc[i].x += av * w.x; acc[i].y += av * w.y;
                    acc[i].z += av * w.z; acc[i].w += av * w.w;
                }
            }
        }
    }

    float ls[4] = {0.f, 0.f, 0.f, 0.f}, ls2[4] = {0.f, 0.f, 0.f, 0.f};
#pragma unroll
    for (int i = 0; i < 4; i++) {
        int gr = row0 + a + 16 * i;
        if (gr < N) {
            *reinterpret_cast<float4*>(&out[(size_t)gr * 64 + 4 * b]) = acc[i];
            if (outpart) {
                float v[4] = { acc[i].x, acc[i].y, acc[i].z, acc[i].w };
#pragma unroll
                for (int j = 0; j < 4; j++) { ls[j] += v[j]; ls2[j] += v[j] * v[j]; }
            }
        }
    }
    if (outpart) {
        __syncthreads();
#pragma unroll
        for (int j = 0; j < 4; j++) { sred[0][a][4 * b + j] = ls[j]; sred[1][a][4 * b + j] = ls2[j]; }
        __syncthreads();
        if (t < 64) {
            float s = 0.f, s2 = 0.f;
#pragma unroll
            for (int aa = 0; aa < 16; aa++) { s += sred[0][aa][t]; s2 += sred[1][aa][t]; }
            outpart[blockIdx.x * 128 + t] = s;
            outpart[blockIdx.x * 128 + 64 + t] = s2;
        }
    }
}

// ---------------------------------------------------------------------------
// bf16 3x tensor-core flash attention (champion R10 version).
// ---------------------------------------------------------------------------
#define FLASH_SMEM_BF (65536 + 16384 + 1024)

__global__ void __launch_bounds__(256, 2) k_flash_bf(
    const __nv_bfloat16* __restrict__ gQh, const __nv_bfloat16* __restrict__ gQl,
    const __nv_bfloat16* __restrict__ gKh, const __nv_bfloat16* __restrict__ gKl,
    const __nv_bfloat16* __restrict__ gVh, const __nv_bfloat16* __restrict__ gVl,
    float* __restrict__ O, int seg_off, int tiles_per_seg, int ksplit,
    float* __restrict__ pO, float* __restrict__ pMS)
{
    extern __shared__ char smc[];
    char* sKV = smc;
    char* sQ  = smc + 65536;
    float* red = (float*)(smc + 65536 + 16384);

    int bx = blockIdx.x;
    int segi = bx / tiles_per_seg;
    int traw = bx - segi * tiles_per_seg;
    int tile = traw / ksplit;
    int si = traw - tile * ksplit;
    int seg = seg_off + segi;
    int q0 = g_seg[seg * 4 + 0], nq = g_seg[seg * 4 + 1];
    int k0 = g_seg[seg * 4 + 2], nk = g_seg[seg * 4 + 3];
    if (tile * 64 >= nq) return;
    int qbase = q0 + tile * 64;
    int nqv = min(64, nq - tile * 64);

    int nkt_tot = (nk + 63) >> 6;
    int per = (nkt_tot + ksplit - 1) / ksplit;
    int kt0 = si * per;
    int kt1 = min(nkt_tot, kt0 + per);
    int nkt = kt1 - kt0;

    int t = threadIdx.x;
    int w = t >> 5, lane = t & 31;
    int qg = w & 3, h = w >> 2;
    int quad = lane >> 2, qi = lane & 3;
    int r0 = qg * 16 + quad, r1 = r0 + 8;

    float oc[32];
#pragma unroll
    for (int i = 0; i < 32; i++) oc[i] = 0.f;
    float rmax0 = -1e30f, rmax1 = -1e30f, rsum0 = 0.f, rsum1 = 0.f;

    unsigned Qh[4][4], Ql[4][4];

    if (nkt > 0) {
        {
#pragma unroll
            for (int j = 0; j < 2; j++) {
                int chunk = t + 256 * j;
                int row = chunk >> 3, jj = chunk & 7;
                cpa16(smu32(sQ + SW(row, jj << 4)),        gQh + (size_t)(qbase + row) * 64 + jj * 8);
                cpa16(smu32(sQ + 8192 + SW(row, jj << 4)), gQl + (size_t)(qbase + row) * 64 + jj * 8);
            }
        }
        CP_COMMIT();
        {
            const __nv_bfloat16* gs[4] = { gKh, gKl, gVh, gVl };
            int kb0 = k0 + kt0 * 64;
#pragma unroll
            for (int a = 0; a < 4; a++)
#pragma unroll
                for (int j = 0; j < 2; j++) {
                    int chunk = t + 256 * j;
                    int row = chunk >> 3, jj = chunk & 7;
                    cpa16(smu32(sKV + a * 8192 + SW(row, jj << 4)),
                          gs[a] + (size_t)(kb0 + row) * 64 + jj * 8);
                }
        }
        CP_COMMIT();
        CP_WAIT1();
        __syncthreads();
        {
            int r = qg * 16 + (lane & 7) + ((lane & 8) ? 8 : 0);
#pragma unroll
            for (int ch = 0; ch < 4; ch++) {
                int cb = ch * 32 + ((lane & 16) ? 16 : 0);
                ldsm4(Qh[ch], smu32(sQ + SW(r, cb)));
                ldsm4(Ql[ch], smu32(sQ + 8192 + SW(r, cb)));
            }
        }

        for (int kt = 0; kt < nkt; kt++) {
            char* sb = sKV + (kt & 1) * 32768;
            __syncthreads();
            if (kt + 1 < nkt) {
                char* nb = sKV + ((kt + 1) & 1) * 32768;
                int kb = k0 + (kt0 + kt + 1) * 64;
                const __nv_bfloat16* gs[4] = { gKh, gKl, gVh, gVl };
#pragma unroll
                for (int a = 0; a < 4; a++)
#pragma unroll
                    for (int j = 0; j < 2; j++) {
                        int chunk = t + 256 * j;
                        int row = chunk >> 3, jj = chunk & 7;
                        cpa16(smu32(nb + a * 8192 + SW(row, jj << 4)),
                              gs[a] + (size_t)(kb + row) * 64 + jj * 8);
                    }
            }
            CP_COMMIT();
            CP_WAIT1();
            __syncthreads();

            int nkv = min(64, nk - (kt0 + kt) * 64);
            char* sKh = sb;
            char* sKl = sb + 8192;
            char* sVh = sb + 16384;
            char* sVl = sb + 24576;

            float c4[4][4];
#pragma unroll
            for (int nt = 0; nt < 4; nt++)
#pragma unroll
                for (int k = 0; k < 4; k++) c4[nt][k] = 0.f;

#pragma unroll
            for (int ch = 0; ch < 4; ch++) {
                unsigned kh[8], kl[8];
                {
                    int r = 32 * h + (lane & 7) + ((lane & 16) ? 8 : 0);
                    int cb = ch * 32 + ((lane & 8) ? 16 : 0);
                    ldsm4(kh,     smu32(sKh + SW(r, cb)));
                    ldsm4(kh + 4, smu32(sKh + SW(r + 16, cb)));
                    ldsm4(kl,     smu32(sKl + SW(r, cb)));
                    ldsm4(kl + 4, smu32(sKl + SW(r + 16, cb)));
                }
#pragma unroll
                for (int nt = 0; nt < 4; nt++) {
                    mma_bf(c4[nt], Qh[ch], &kh[2 * nt]);
                    mma_bf(c4[nt], Qh[ch], &kl[2 * nt]);
                    mma_bf(c4[nt], Ql[ch], &kh[2 * nt]);
                }
            }

            if (nkv < 64) {
#pragma unroll
                for (int nt = 0; nt < 4; nt++) {
                    int colb = 32 * h + 8 * nt + 2 * qi;
#pragma unroll
                    for (int k = 0; k < 4; k++)
                        if (colb + (k & 1) >= nkv) c4[nt][k] = -1e30f;
                }
            }

            float mx0 = -1e30f, mx1 = -1e30f;
#pragma unroll
            for (int nt = 0; nt < 4; nt++) {
                mx0 = fmaxf(mx0, fmaxf(c4[nt][0], c4[nt][1]));
                mx1 = fmaxf(mx1, fmaxf(c4[nt][2], c4[nt][3]));
            }
            mx0 = fmaxf(mx0, __shfl_xor_sync(0xffffffffu, mx0, 1));
            mx0 = fmaxf(mx0, __shfl_xor_sync(0xffffffffu, mx0, 2));
            mx1 = fmaxf(mx1, __shfl_xor_sync(0xffffffffu, mx1, 1));
            mx1 = fmaxf(mx1, __shfl_xor_sync(0xffffffffu, mx1, 2));
            float mnew0 = fmaxf(rmax0, mx0);
            float mnew1 = fmaxf(rmax1, mx1);
            float corr0 = __expf(rmax0 - mnew0);
            float corr1 = __expf(rmax1 - mnew1);
            rmax0 = mnew0; rmax1 = mnew1;

            float ps0 = 0.f, ps1 = 0.f;
#pragma unroll
            for (int nt = 0; nt < 4; nt++) {
                float p0 = __expf(c4[nt][0] - mnew0);
                float p1 = __expf(c4[nt][1] - mnew0);
                float p2 = __expf(c4[nt][2] - mnew1);
                float p3 = __expf(c4[nt][3] - mnew1);
                ps0 += p0 + p1; ps1 += p2 + p3;
                c4[nt][0] = p0; c4[nt][1] = p1; c4[nt][2] = p2; c4[nt][3] = p3;
            }
            ps0 += __shfl_xor_sync(0xffffffffu, ps0, 1);
            ps0 += __shfl_xor_sync(0xffffffffu, ps0, 2);
            ps1 += __shfl_xor_sync(0xffffffffu, ps1, 1);
            ps1 += __shfl_xor_sync(0xffffffffu, ps1, 2);
            rsum0 = rsum0 * corr0 + ps0;
            rsum1 = rsum1 * corr1 + ps1;
#pragma unroll
            for (int nt = 0; nt < 8; nt++) {
                oc[nt * 4 + 0] *= corr0; oc[nt * 4 + 1] *= corr0;
                oc[nt * 4 + 2] *= corr1; oc[nt * 4 + 3] *= corr1;
            }

#pragma unroll
            for (int ck = 0; ck < 2; ck++) {
                unsigned pa_h[4], pa_l[4];
                bf_split2(c4[2 * ck][0],     c4[2 * ck][1],     pa_h[0], pa_l[0]);
                bf_split2(c4[2 * ck][2],     c4[2 * ck][3],     pa_h[1], pa_l[1]);
                bf_split2(c4[2 * ck + 1][0], c4[2 * ck + 1][1], pa_h[2], pa_l[2]);
                bf_split2(c4[2 * ck + 1][2], c4[2 * ck + 1][3], pa_h[3], pa_l[3]);
                int key0 = 32 * h + 16 * ck;
#pragma unroll
                for (int cc = 0; cc < 4; cc++) {
                    unsigned vh[4], vl[4];
                    {
                        int r = key0 + (lane & 7) + ((lane & 8) ? 8 : 0);
                        int cb = cc * 32 + ((lane & 16) ? 16 : 0);
                        ldsm4t(vh, smu32(sVh + SW(r, cb)));
                        ldsm4t(vl, smu32(sVl + SW(r, cb)));
                    }
                    mma_bf(&oc[(2 * cc) * 4], pa_h, &vh[0]);
                    mma_bf(&oc[(2 * cc) * 4], pa_h, &vl[0]);
                    mma_bf(&oc[(2 * cc) * 4], pa_l, &vh[0]);
                    mma_bf(&oc[(2 * cc + 1) * 4], pa_h, &vh[2]);
                    mma_bf(&oc[(2 * cc + 1) * 4], pa_h, &vl[2]);
                    mma_bf(&oc[(2 * cc + 1) * 4], pa_l, &vh[2]);
                }
            }
        }
    }

    if (qi == 0) {
        red[h * 64 + r0] = rmax0;       red[h * 64 + r1] = rmax1;
        red[128 + h * 64 + r0] = rsum0; red[128 + h * 64 + r1] = rsum1;
    }
    __syncthreads();

    float m0a = red[r0], m1a = red[64 + r0];
    float mma_ = fmaxf(m0a, m1a);
    float fh_a = __expf(((h == 0) ? m0a : m1a) - mma_);
    float stot_a = red[128 + r0] * __expf(m0a - mma_) + red[192 + r0] * __expf(m1a - mma_);
    float m0b = red[r1], m1b = red[64 + r1];
    float mmb_ = fmaxf(m0b, m1b);
    float fh_b = __expf(((h == 0) ? m0b : m1b) - mmb_);
    float stot_b = red[128 + r1] * __expf(m0b - mmb_) + red[192 + r1] * __expf(m1b - mmb_);

    float* sO = (float*)sQ;
    if (h == 1) {
#pragma unroll
        for (int nt = 0; nt < 8; nt++) {
            int colb = 8 * nt + 2 * qi;
            sO[r0 * 64 + colb]     = oc[nt * 4 + 0] * fh_a;
            sO[r0 * 64 + colb + 1] = oc[nt * 4 + 1] * fh_a;
            sO[r1 * 64 + colb]     = oc[nt * 4 + 2] * fh_b;
            sO[r1 * 64 + colb + 1] = oc[nt * 4 + 3] * fh_b;
        }
    }
    __syncthreads();
    if (h == 0) {
        if (ksplit == 1) {
            float inva = fh_a / stot_a, invb = fh_b / stot_b;
            float ja = 1.f / stot_a, jb = 1.f / stot_b;
#pragma unroll
            for (int nt = 0; nt < 8; nt++) {
                int colb = 8 * nt + 2 * qi;
                if (r0 < nqv) {
                    O[(size_t)(qbase + r0) * 64 + colb]     = oc[nt * 4 + 0] * inva + sO[r0 * 64 + colb] * ja;
                    O[(size_t)(qbase + r0) * 64 + colb + 1] = oc[nt * 4 + 1] * inva + sO[r0 * 64 + colb + 1] * ja;
                }
                if (r1 < nqv) {
                    O[(size_t)(qbase + r1) * 64 + colb]     = oc[nt * 4 + 2] * invb + sO[r1 * 64 + colb] * jb;
                    O[(size_t)(qbase + r1) * 64 + colb + 1] = oc[nt * 4 + 3] * invb + sO[r1 * 64 + colb + 1] * jb;
                }
            }
        } else {
            float* pOo = pO + (size_t)si * CELLS;
            float* pM  = pMS + (size_t)si * 2 * NDMAX;
#pragma unroll
            for (int nt = 0; nt < 8; nt++) {
                int colb = 8 * nt + 2 * qi;
                if (r0 < nqv) {
                    pOo[(size_t)(qbase + r0) * 64 + colb]     = oc[nt * 4 + 0] * fh_a + sO[r0 * 64 + colb];
                    pOo[(size_t)(qbase + r0) * 64 + colb + 1] = oc[nt * 4 + 1] * fh_a + sO[r0 * 64 + colb + 1];
                }
                if (r1 < nqv) {
                    pOo[(size_t)(qbase + r1) * 64 + colb]     = oc[nt * 4 + 2] * fh_b + sO[r1 * 64 + colb];
                    pOo[(size_t)(qbase + r1) * 64 + colb + 1] = oc[nt * 4 + 3] * fh_b + sO[r1 * 64 + colb + 1];
                }
            }
            if (qi == 0) {
                if (r0 < nqv) { pM[(qbase + r0) * 2] = mma_; pM[(qbase + r0) * 2 + 1] = stot_a; }
                if (r1 < nqv) { pM[(qbase + r1) * 2] = mmb_; pM[(qbase + r1) * 2 + 1] = stot_b; }
            }
        }
    }
}

// ---------------------------------------------------------------------------
// BN kernels
// ---------------------------------------------------------------------------
__global__ void k_bnstats_add(const float* __restrict__ X, const float* __restrict__ Y,
                              float* __restrict__ S, int N, float* __restrict__ part)
{
    __shared__ float sh[2][4][64];
    int c = threadIdx.x & 63, rg = threadIdx.x >> 6;
    int stride = gridDim.x * 4;
    float s = 0.f, s2 = 0.f;
    for (int r = blockIdx.x * 4 + rg; r < N; r += stride) {
        float v = X[r * 64 + c] + Y[r * 64 + c];
        S[r * 64 + c] = v;
        s += v; s2 += v * v;
    }
    sh[0][rg][c] = s; sh[1][rg][c] = s2;
    __syncthreads();
    if (threadIdx.x < 64) {
        float ts = sh[0][0][c] + sh[0][1][c] + sh[0][2][c] + sh[0][3][c];
        float t2 = sh[1][0][c] + sh[1][1][c] + sh[1][2][c] + sh[1][3][c];
        part[blockIdx.x * 128 + c] = ts;
        part[blockIdx.x * 128 + 64 + c] = t2;
    }
}

__global__ void __launch_bounds__(256) k_bnapply_stats(
    const float* __restrict__ X, const float* __restrict__ Res,
    const float* __restrict__ gamma, const float* __restrict__ beta,
    const float* __restrict__ sp, int snb,
    float* __restrict__ Out, int N, float* __restrict__ outpart)
{
    __shared__ float sh[2][4][64];
    __shared__ float sa[64], sb[64];
    int c = threadIdx.x & 63, rg = threadIdx.x >> 6;
    int row0 = blockIdx.x * 64;
    if (threadIdx.x < 64) bn_coeff(sp, snb, N, c, gamma[c], beta[c], sa[c], sb[c]);
    __syncthreads();
    float A = sa[c], Bc = sb[c];
    float s = 0.f, s2 = 0.f;
#pragma unroll
    for (int i = 0; i < 16; i++) {
        int r = row0 + rg + 4 * i;
        if (r < N) {
            float y = X[r * 64 + c] * A + Bc + Res[r * 64 + c];
            Out[r * 64 + c] = y;
            s += y; s2 += y * y;
        }
    }
    sh[0][rg][c] = s; sh[1][rg][c] = s2;
    __syncthreads();
    if (threadIdx.x < 64) {
        float ts = sh[0][0][c] + sh[0][1][c] + sh[0][2][c] + sh[0][3][c];
        float t2 = sh[1][0][c] + sh[1][1][c] + sh[1][2][c] + sh[1][3][c];
        outpart[blockIdx.x * 128 + c] = ts;
        outpart[blockIdx.x * 128 + 64 + c] = t2;
    }
}

__global__ void __launch_bounds__(256) k_bnapply_fin(
    const float* __restrict__ X,
    const float* __restrict__ gamma, const float* __restrict__ beta,
    const float* __restrict__ sp, int snb,
    float* __restrict__ Out, int N)
{
    __shared__ float sa[64], sb[64];
    int c = threadIdx.x & 63, rg = threadIdx.x >> 6;
    int row0 = blockIdx.x * 64;
    if (threadIdx.x < 64) bn_coeff(sp, snb, N, c, gamma[c], beta[c], sa[c], sb[c]);
    __syncthreads();
    float A = sa[c], Bc = sb[c];
#pragma unroll
    for (int i = 0; i < 16; i++) {
        int r = row0 + rg + 4 * i;
        if (r < N) Out[r * 64 + c] = fmaxf(X[r * 64 + c] * A + Bc, 0.f);
    }
}

// ---------------------------------------------------------------------------
extern "C" void kernel_launch(void* const* d_in, const int* in_sizes, int n_in,
                              void* d_out, int out_size)
{
    const float* xdec  = (const float*)d_in[0];
    const float* xenc  = (const float*)d_in[1];
    const float* Wp1   = (const float*)d_in[2];
    const float* Wq    = (const float*)d_in[3];
    const float* Wk    = (const float*)d_in[4];
    const float* Wv    = (const float*)d_in[5];
    const float* Wt    = (const float*)d_in[6];
    const float* Wq1   = (const float*)d_in[7];
    const float* Wk1   = (const float*)d_in[8];
    const float* Wv1   = (const float*)d_in[9];
    const float* Wdown = (const float*)d_in[10];
    const float* W3t   = (const float*)d_in[11];
    const float* W3a   = (const float*)d_in[12];
    const float* W3b   = (const float*)d_in[13];
    const float* gam   = (const float*)d_in[14];
    const float* bet   = (const float*)d_in[15];
    const int* nbr     = (const int*)d_in[16];
    const int* kv_nbr  = (const int*)d_in[17];
    const int* pad_idx = (const int*)d_in[18];

    int nd = in_sizes[0] / 64;
    int ne = in_sizes[1] / 64;
    int lq = in_sizes[18] / NBATCH;
    float* out = (float*)d_out;

    float* base = nullptr;   cudaGetSymbolAddress((void**)&base, g_buf);
    float* pob = nullptr;    cudaGetSymbolAddress((void**)&pob, g_po);
    float* pmsb = nullptr;   cudaGetSymbolAddress((void**)&pmsb, g_pms);
    float* partb = nullptr;  cudaGetSymbolAddress((void**)&partb, g_part);
    __nv_bfloat16* bfb = nullptr; cudaGetSymbolAddress((void**)&bfb, g_bf);
    __nv_bfloat16* wtb = nullptr; cudaGetSymbolAddress((void**)&wtb, g_wtb);

    float* B[15];
    for (int i = 0; i < 15; i++) B[i] = base + (size_t)i * CELLS;
    __nv_bfloat16* BF[6];
    for (int i = 0; i < 6; i++) BF[i] = bfb + (size_t)i * PADCELLS;
    __nv_bfloat16* WT[8];
    for (int i = 0; i < 8; i++) WT[i] = wtb + (size_t)i * 8192;
    float* partA = partb;
    float* partB = partb + 256 * 128;

    cudaFuncSetAttribute(k_flash_bf, cudaFuncAttributeMaxDynamicSharedMemorySize, FLASH_SMEM_BF);
    cudaFuncSetAttribute(k_gconv, cudaFuncAttributeMaxDynamicSharedMemorySize, GC_SMEM);

    dim3 thr(256);
    int gbd = (nd + 63) / 64;
    int gbe = (ne + 63) / 64;
    int gx = gbd > gbe ? gbd : gbe;

    // ---- init ----
    k_init<<<9, thr>>>(Wp1, Wq, Wk, Wv, Wt, Wq1, Wk1, Wv1, pad_idx, nd, ne, lq);

    // ---- Stage 1 ----
    {
        TJobs JJ = {};
        JJ.j[0].A = xdec; JJ.j[0].Wbf = WT[0]; JJ.j[0].C = B[0]; JJ.j[0].N = nd; JJ.j[0].mode = 0;
        JJ.j[1].A = xdec; JJ.j[1].Wbf = WT[1]; JJ.j[1].hi = BF[0]; JJ.j[1].lo = BF[1]; JJ.j[1].N = nd; JJ.j[1].mode = 0;
        JJ.j[2].A = xenc; JJ.j[2].Wbf = WT[2]; JJ.j[2].hi = BF[2]; JJ.j[2].lo = BF[3]; JJ.j[2].N = ne; JJ.j[2].mode = 0;
        JJ.j[3].A = xenc; JJ.j[3].Wbf = WT[3]; JJ.j[3].hi = BF[4]; JJ.j[3].lo = BF[5]; JJ.j[3].N = ne; JJ.j[3].mode = 0;
        k_tgemm<<<dim3(gx, 4), thr>>>(JJ);
    }
    k_flash_bf<<<gbd * KS, thr, FLASH_SMEM_BF>>>(BF[0], BF[1], BF[2], BF[3], BF[4], BF[5],
                                                 B[4], 0, gbd * KS, KS, pob, pmsb);
    {   // xr = merge(splitK) @ Wt (+stats A)
        TJobs JJ = {};
        JJ.j[0].pO = pob; JJ.j[0].pMS = pmsb; JJ.j[0].Wbf = WT[4];
        JJ.j[0].C = B[5]; JJ.j[0].part = partA; JJ.j[0].N = nd; JJ.j[0].mode = 3;
        k_tgemm<<<dim3(gbd, 1), thr>>>(JJ);
    }
    {   // xd = bn(xr)+xd0 -> B6 ; q1 = xd@Wq1 -> B7 + BF0/1
        TJobs JJ = {};
        JJ.j[0].A = B[5]; JJ.j[0].Res = B[0]; JJ.j[0].bg = gam + 0; JJ.j[0].bb = bet + 0;
        JJ.j[0].sp = partA; JJ.j[0].snb = gbd; JJ.j[0].Aout = B[6];
        JJ.j[0].Wbf = WT[5]; JJ.j[0].C = B[7]; JJ.j[0].hi = BF[0]; JJ.j[0].lo = BF[1];
        JJ.j[0].N = nd; JJ.j[0].mode = 2;
        k_tgemm<<<dim3(gbd, 1), thr>>>(JJ);
    }

    // ---- Stage 2 ----
    k_gconv<<<gbd, thr, GC_SMEM>>>(B[7], kv_nbr, 8, Wdown, B[8], nd,
                                   partA, nullptr, 0, nullptr, nullptr);
    {   // k1, v1 = bn(kv) @ {Wk1, Wv1}
        TJobs JJ = {};
        JJ.j[0].A = B[8]; JJ.j[0].Wbf = WT[6]; JJ.j[0].hi = BF[2]; JJ.j[0].lo = BF[3];
        JJ.j[0].bg = gam + 64; JJ.j[0].bb = bet + 64; JJ.j[0].sp = partA; JJ.j[0].snb = gbd;
        JJ.j[0].N = nd; JJ.j[0].mode = 1;
        JJ.j[1] = JJ.j[0];
        JJ.j[1].Wbf = WT[7]; JJ.j[1].hi = BF[4]; JJ.j[1].lo = BF[5];
        k_tgemm<<<dim3(gbd, 2), thr>>>(JJ);
    }
    int tps = (lq + 63) / 64;
    k_flash_bf<<<NBATCH * tps, thr, FLASH_SMEM_BF>>>(BF[0], BF[1], BF[2], BF[3], BF[4], BF[5],
                                                     B[12], 1, tps, 1, nullptr, nullptr);
    k_gconv<<<gbd, thr, GC_SMEM>>>(B[12], nbr, 27, W3t, B[13], nd,
                                   partA, nullptr, 0, nullptr, nullptr);
    k_bnapply_stats<<<gbd, thr>>>(B[13], B[6], gam + 128, bet + 128, partA, gbd,
                                  B[14], nd, partB);

    // ---- Res block ----
    k_gconv<<<gbd, thr, GC_SMEM>>>(B[14], nbr, 27, W3a, B[1], nd,
                                   partA, partB, gbd, gam + 192, bet + 192);
    k_gconv<<<gbd, thr, GC_SMEM>>>(B[1], nbr, 27, W3b, B[3], nd,
                                   nullptr, partA, gbd, gam + 256, bet + 256);
    k_bnstats_add<<<gbd, thr>>>(B[14], B[3], B[4], nd, partA);
    k_bnapply_fin<<<gbd, thr>>>(B[4], gam + 320, bet + 320, partA, gbd, out, nd);
}

// round 17
// speedup vs baseline: 1.0079x; 1.0079x over previous
#include <cuda_runtime.h>
#include <cuda_bf16.h>
#include <math.h>

#define NF 64
#define NBATCH 8
#define NDMAX 12288
#define CELLS (NDMAX * NF)
#define PADCELLS (CELLS + 64 * 64)
#define KS 3

__device__ float g_buf[15][CELLS];
__device__ float g_po[KS][CELLS];
__device__ float g_pms[KS][2 * NDMAX];
__device__ __nv_bfloat16 g_bf[6][PADCELLS];   // Qhi Qlo Khi Klo Vhi Vlo
__device__ float g_part[2][256 * 128];        // alternating BN partial buffers
__device__ int   g_seg[64];
__device__ __nv_bfloat16 g_wtb[8 * 8192];     // 8 weight mats, bf16 hi+lo, swizzled

// ---------------------------------------------------------------------------
// Helpers
// ---------------------------------------------------------------------------
__device__ __forceinline__ int SW(int r, int cb) {
    return r * 128 + (cb ^ ((r & 7) << 4));
}
__device__ __forceinline__ unsigned smu32(const void* p) {
    return (unsigned)__cvta_generic_to_shared(p);
}
__device__ __forceinline__ void cpa16(unsigned dst, const void* src) {
    asm volatile("cp.async.ca.shared.global [%0], [%1], 16;" :: "r"(dst), "l"(src) : "memory");
}
#define CP_COMMIT() asm volatile("cp.async.commit_group;" ::: "memory")
#define CP_WAIT1()  asm volatile("cp.async.wait_group 1;" ::: "memory")
#define CP_WAIT0()  asm volatile("cp.async.wait_group 0;" ::: "memory")

__device__ __forceinline__ void ldsm4(unsigned r[4], unsigned a) {
    asm volatile("ldmatrix.sync.aligned.m8n8.x4.shared.b16 {%0,%1,%2,%3}, [%4];"
                 : "=r"(r[0]), "=r"(r[1]), "=r"(r[2]), "=r"(r[3]) : "r"(a));
}
__device__ __forceinline__ void ldsm4t(unsigned r[4], unsigned a) {
    asm volatile("ldmatrix.sync.aligned.m8n8.x4.trans.shared.b16 {%0,%1,%2,%3}, [%4];"
                 : "=r"(r[0]), "=r"(r[1]), "=r"(r[2]), "=r"(r[3]) : "r"(a));
}
__device__ __forceinline__ void mma_bf(float c[4], const unsigned a[4], const unsigned b[2]) {
    asm volatile(
        "mma.sync.aligned.m16n8k16.row.col.f32.bf16.bf16.f32 "
        "{%0,%1,%2,%3}, {%4,%5,%6,%7}, {%8,%9}, {%0,%1,%2,%3};"
        : "+f"(c[0]), "+f"(c[1]), "+f"(c[2]), "+f"(c[3])
        : "r"(a[0]), "r"(a[1]), "r"(a[2]), "r"(a[3]), "r"(b[0]), "r"(b[1]));
}

__device__ __forceinline__ void bf_split(float v, unsigned short& hb, unsigned short& lb) {
    __nv_bfloat16 h = __float2bfloat16(v);
    hb = __bfloat16_as_ushort(h);
    lb = __bfloat16_as_ushort(__float2bfloat16(v - __bfloat162float(h)));
}
__device__ __forceinline__ void bf_split2(float a, float b, unsigned& hw, unsigned& lw) {
    unsigned short ha, la, hb, lb;
    bf_split(a, ha, la);
    bf_split(b, hb, lb);
    hw = (unsigned)ha | ((unsigned)hb << 16);
    lw = (unsigned)la | ((unsigned)lb << 16);
}

// per-column BN coefficients from partial buffer: y = x*A + B
__device__ __forceinline__ void bn_coeff(const float* part, int nblk, int N, int c,
                                         float g, float be, float& A, float& Bc) {
    float s = 0.f, s2 = 0.f;
    for (int b = 0; b < nblk; b++) { s += part[b * 128 + c]; s2 += part[b * 128 + 64 + c]; }
    float mu = s / (float)N;
    float rs = rsqrtf(s2 / (float)N - mu * mu + 1e-4f);
    A = rs * g;
    Bc = be - mu * A;
}

// ---------------------------------------------------------------------------
// Init: blocks 0-7 convert weights to swizzled bf16 hi/lo; block 8 seg prep.
// slots: 0 Wp1, 1 Wc=Wp1@Wq, 2 Wk, 3 Wv, 4 Wt, 5 Wq1, 6 Wk1, 7 Wv1
// ---------------------------------------------------------------------------
__global__ void __launch_bounds__(256) k_init(
    const float* __restrict__ Wp1, const float* __restrict__ Wq,
    const float* __restrict__ Wk,  const float* __restrict__ Wv,
    const float* __restrict__ Wt,  const float* __restrict__ Wq1,
    const float* __restrict__ Wk1, const float* __restrict__ Wv1,
    const int* __restrict__ pad_idx, int nd, int ne, int lq)
{
    int t = threadIdx.x;
    int blk = blockIdx.x;
    if (blk == 8) {
        int w = t >> 5, lane = t & 31;
        if (w < NBATCH) {
            int cnt = 0;
            for (int l = lane; l < lq; l += 32)
                cnt += (pad_idx[w * lq + l] >= 0) ? 1 : 0;
#pragma unroll
            for (int o = 16; o > 0; o >>= 1) cnt += __shfl_xor_sync(0xffffffffu, cnt, o);
            if (lane == 0) {
                int s = pad_idx[w * lq];
                g_seg[(1 + w) * 4 + 0] = s;
                g_seg[(1 + w) * 4 + 1] = cnt;
                g_seg[(1 + w) * 4 + 2] = s;
                g_seg[(1 + w) * 4 + 3] = cnt;
            }
        }
        if (t == 0) { g_seg[0] = 0; g_seg[1] = nd; g_seg[2] = 0; g_seg[3] = ne; }
        return;
    }

    char* dst = (char*)(g_wtb + (size_t)blk * 8192);

    if (blk == 1) {
        __shared__ float s1[4096], s2[4096];
        for (int i = t; i < 4096; i += 256) { s1[i] = Wp1[i]; s2[i] = Wq[i]; }
        __syncthreads();
        int r = t >> 2, c0 = (t & 3) * 16;
        float acc[16];
#pragma unroll
        for (int j = 0; j < 16; j++) acc[j] = 0.f;
        for (int m = 0; m < 64; m++) {
            float a = s1[r * 64 + m];
#pragma unroll
            for (int j = 0; j < 16; j++) acc[j] += a * s2[m * 64 + c0 + j];
        }
#pragma unroll
        for (int j = 0; j < 16; j++) {
            unsigned short hb, lb;
            bf_split(acc[j], hb, lb);
            int off = SW(r, (c0 + j) * 2);
            *(unsigned short*)(dst + off) = hb;
            *(unsigned short*)(dst + 8192 + off) = lb;
        }
        return;
    }

    const float* src = Wp1;
    if (blk == 2) src = Wk;
    else if (blk == 3) src = Wv;
    else if (blk == 4) src = Wt;
    else if (blk == 5) src = Wq1;
    else if (blk == 6) src = Wk1;
    else if (blk == 7) src = Wv1;
    for (int e = t; e < 4096; e += 256) {
        int r = e >> 6, c = e & 63;
        unsigned short hb, lb;
        bf_split(src[e], hb, lb);
        int off = SW(r, c * 2);
        *(unsigned short*)(dst + off) = hb;
        *(unsigned short*)(dst + 8192 + off) = lb;
    }
}

// ---------------------------------------------------------------------------
// Unified tensor-core GEMM (static smem, direct A loads).
// mode 0: A plain; 1: bn(A); 2: bn(X)+Res (writes Aout); 3: split-K merge.
// ---------------------------------------------------------------------------
struct TJob {
    const float* A; const float* Res;
    const float* pO; const float* pMS;
    const __nv_bfloat16* Wbf;
    float* C; float* Aout;
    __nv_bfloat16* hi; __nv_bfloat16* lo;
    const float* bg; const float* bb; const float* sp; int snb;
    float* part; int N; int mode;
};
struct TJobs { TJob j[4]; };

__global__ void __launch_bounds__(256) k_tgemm(TJobs JJ)
{
    TJob J = JJ.j[blockIdx.y];
    int N = J.N;
    int row0 = blockIdx.x * 64;
    if (row0 >= N) return;

    __shared__ char sAh[8192];
    __shared__ char sAl[8192];
    __shared__ char sWb[16384];
    __shared__ float saux[64 * 3];
    __shared__ float sred[2][4][64];
    int t = threadIdx.x;

    {
        const char* ws = (const char*)J.Wbf;
#pragma unroll
        for (int q = 0; q < 4; q++) {
            int ch = t + 256 * q;
            cpa16(smu32(sWb + ch * 16), ws + ch * 16);
        }
    }
    CP_COMMIT();

    if (t < 64) {
        if (J.mode == 1 || J.mode == 2) {
            bn_coeff(J.sp, J.snb, N, t, J.bg[t], J.bb[t], saux[t], saux[64 + t]);
        } else if (J.mode == 3) {
            int gr = row0 + t;
            if (gr < N) {
                float m[KS], s[KS];
#pragma unroll
                for (int i = 0; i < KS; i++) {
                    m[i] = J.pMS[(size_t)i * 2 * NDMAX + gr * 2];
                    s[i] = J.pMS[(size_t)i * 2 * NDMAX + gr * 2 + 1];
                }
                float mx = m[0];
#pragma unroll
                for (int i = 1; i < KS; i++) mx = fmaxf(mx, m[i]);
                float e[KS], denom = 0.f;
#pragma unroll
                for (int i = 0; i < KS; i++) { e[i] = __expf(m[i] - mx); denom += s[i] * e[i]; }
                float inv = 1.f / denom;
#pragma unroll
                for (int i = 0; i < KS; i++) saux[i * 64 + t] = e[i] * inv;
            } else {
#pragma unroll
                for (int i = 0; i < KS; i++) saux[i * 64 + t] = 0.f;
            }
        } else {
            saux[t] = 1.f; saux[64 + t] = 0.f;
        }
    }
    __syncthreads();

    // Build A bf16 hi/lo planes
#pragma unroll
    for (int i = 0; i < 16; i++) {
        int e = t + 256 * i;
        int r = e >> 6, c = e & 63;
        int gr = row0 + r;
        float v = 0.f;
        if (gr < N) {
            if (J.mode == 3) {
#pragma unroll
                for (int k = 0; k < KS; k++)
                    v += J.pO[(size_t)k * CELLS + (size_t)gr * 64 + c] * saux[k * 64 + r];
            } else if (J.mode == 2) {
                v = J.A[(size_t)gr * 64 + c] * saux[c] + saux[64 + c] + J.Res[(size_t)gr * 64 + c];
                J.Aout[(size_t)gr * 64 + c] = v;
            } else {
                v = J.A[(size_t)gr * 64 + c] * saux[c] + saux[64 + c];
            }
        }
        unsigned short hb, lb;
        bf_split(v, hb, lb);
        int off = SW(r, c * 2);
        *(unsigned short*)(sAh + off) = hb;
        *(unsigned short*)(sAl + off) = lb;
    }
    CP_WAIT0();
    __syncthreads();

    int lane = t & 31, w = t >> 5;
    int mi = w & 3, nh = w >> 2;
    float c4[4][4];
#pragma unroll
    for (int nt = 0; nt < 4; nt++)
#pragma unroll
        for (int k = 0; k < 4; k++) c4[nt][k] = 0.f;

    char* wh = sWb;
    char* wl = sWb + 8192;
#pragma unroll
    for (int ch = 0; ch < 4; ch++) {
        unsigned ah[4], al[4];
        {
            int r = mi * 16 + (lane & 7) + ((lane & 8) ? 8 : 0);
            int cb = ch * 32 + ((lane & 16) ? 16 : 0);
            ldsm4(ah, smu32(sAh + SW(r, cb)));
            ldsm4(al, smu32(sAl + SW(r, cb)));
        }
        unsigned b0h[4], b1h[4], b0l[4], b1l[4];
        {
            int r2 = ch * 16 + (lane & 7) + ((lane & 8) ? 8 : 0);
            int cb0 = (nh * 2 + 0) * 32 + ((lane & 16) ? 16 : 0);
            int cb1 = (nh * 2 + 1) * 32 + ((lane & 16) ? 16 : 0);
            ldsm4t(b0h, smu32(wh + SW(r2, cb0)));
            ldsm4t(b1h, smu32(wh + SW(r2, cb1)));
            ldsm4t(b0l, smu32(wl + SW(r2, cb0)));
            ldsm4t(b1l, smu32(wl + SW(r2, cb1)));
        }
        mma_bf(c4[0], ah, &b0h[0]); mma_bf(c4[0], ah, &b0l[0]); mma_bf(c4[0], al, &b0h[0]);
        mma_bf(c4[1], ah, &b0h[2]); mma_bf(c4[1], ah, &b0l[2]); mma_bf(c4[1], al, &b0h[2]);
        mma_bf(c4[2], ah, &b1h[0]); mma_bf(c4[2], ah, &b1l[0]); mma_bf(c4[2], al, &b1h[0]);
        mma_bf(c4[3], ah, &b1h[2]); mma_bf(c4[3], ah, &b1l[2]); mma_bf(c4[3], al, &b1h[2]);
    }
    __syncthreads();

    float* sO = (float*)sAh;
    int quad = lane >> 2, qi = lane & 3;
    int r0 = mi * 16 + quad, r1 = r0 + 8;
#pragma unroll
    for (int nt = 0; nt < 4; nt++) {
        int colb = nh * 32 + nt * 8 + 2 * qi;
        sO[r0 * 64 + colb]     = c4[nt][0];
        sO[r0 * 64 + colb + 1] = c4[nt][1];
        sO[r1 * 64 + colb]     = c4[nt][2];
        sO[r1 * 64 + colb + 1] = c4[nt][3];
    }
    __syncthreads();

    int c = t & 63, rg = t >> 6;
    float s = 0.f, s2 = 0.f;
#pragma unroll
    for (int i = 0; i < 16; i++) {
        int r = rg * 16 + i;
        int gr = row0 + r;
        if (gr < N) {
            float v = sO[r * 64 + c];
            if (J.C) J.C[(size_t)gr * 64 + c] = v;
            if (J.hi) {
                unsigned short hb, lb;
                bf_split(v, hb, lb);
                *(unsigned short*)&J.hi[(size_t)gr * 64 + c] = hb;
                *(unsigned short*)&J.lo[(size_t)gr * 64 + c] = lb;
            }
            s += v; s2 += v * v;
        }
    }
    if (J.part) {
        sred[0][rg][c] = s; sred[1][rg][c] = s2;
        __syncthreads();
        if (t < 64) {
            float ts = sred[0][0][c] + sred[0][1][c] + sred[0][2][c] + sred[0][3][c];
            float t2 = sred[1][0][c] + sred[1][1][c] + sred[1][2][c] + sred[1][3][c];
            J.part[blockIdx.x * 128 + c] = ts;
            J.part[blockIdx.x * 128 + 64 + c] = t2;
        }
    }
}

// ---------------------------------------------------------------------------
// Pipelined scalar rulebook sparse conv; optional input BN+ReLU, optional
// output BN stats.
// ---------------------------------------------------------------------------
#define GC_SMEM ((2 * 4096 + 2 * 64 * 68) * 4)

__global__ void __launch_bounds__(256) k_gconv(
    const float* __restrict__ F, const int* __restrict__ idx, int K,
    const float* __restrict__ W, float* __restrict__ out, int N,
    float* __restrict__ outpart,
    const float* __restrict__ statpart, int snb,
    const float* __restrict__ bg, const float* __restrict__ bb)
{
    extern __shared__ float dsm[];
    float* sW2 = dsm;
    float* sF2 = dsm + 2 * 4096;
    __shared__ int sIdxAll[27 * 64];
    __shared__ float sred[2][16][64];
    __shared__ float sa[64], sb[64];
    int t = threadIdx.x;
    int row0 = blockIdx.x * 64;
    int a = t >> 4, b = t & 15;

    if (bg && t < 64) bn_coeff(statpart, snb, N, t, bg[t], bb[t], sa[t], sb[t]);
    for (int i = t; i < 64 * K; i += 256) {
        int r = i / K, k = i - r * K;
        int gr = row0 + r;
        sIdxAll[k * 64 + r] = (gr < N) ? idx[gr * K + k] : -1;
    }
    __syncthreads();

    int rr = t >> 2, c0 = t & 3;
    {
        char* wd = (char*)sW2;
        const float* ws = W;
#pragma unroll
        for (int q = 0; q < 4; q++) {
            int c = t + 256 * q;
            cpa16(smu32(wd + c * 16), ws + c * 4);
        }
        int j = sIdxAll[rr];
        if (j >= 0) {
            char* fd = (char*)sF2;
#pragma unroll
            for (int q = 0; q < 4; q++)
                cpa16(smu32(fd + rr * 272 + c0 * 64 + q * 16), F + (size_t)j * 64 + c0 * 16 + q * 4);
        }
    }
    CP_COMMIT();

    float4 acc[4];
#pragma unroll
    for (int i = 0; i < 4; i++) acc[i] = make_float4(0.f, 0.f, 0.f, 0.f);

    for (int k = 0; k < K; k++) {
        __syncthreads();
        if (k + 1 < K) {
            int nb = (k + 1) & 1;
            char* wd = (char*)(sW2 + nb * 4096);
            const float* ws = W + (size_t)(k + 1) * 4096;
#pragma unroll
            for (int q = 0; q < 4; q++) {
                int c = t + 256 * q;
                cpa16(smu32(wd + c * 16), ws + c * 4);
            }
            int j = sIdxAll[(k + 1) * 64 + rr];
            if (j >= 0) {
                char* fd = (char*)(sF2 + nb * 4352);
#pragma unroll
                for (int q = 0; q < 4; q++)
                    cpa16(smu32(fd + rr * 272 + c0 * 64 + q * 16), F + (size_t)j * 64 + c0 * 16 + q * 4);
            }
        }
        CP_COMMIT();
        CP_WAIT1();
        __syncthreads();

        int cb = k & 1;
        float* sW = sW2 + cb * 4096;
        float* sF = sF2 + cb * 4352;
        const int* sIdx = sIdxAll + k * 64;

        if (bg) {
            int j = sIdx[rr];
            if (j >= 0) {
#pragma unroll
                for (int q = 0; q < 4; q++) {
                    int c = c0 * 16 + q * 4;
                    float4 v = *reinterpret_cast<float4*>(&sF[rr * 68 + c]);
                    v.x = fmaxf(v.x * sa[c] + sb[c], 0.f);
                    v.y = fmaxf(v.y * sa[c + 1] + sb[c + 1], 0.f);
                    v.z = fmaxf(v.z * sa[c + 2] + sb[c + 2], 0.f);
                    v.w = fmaxf(v.w * sa[c + 3] + sb[c + 3], 0.f);
                    *reinterpret_cast<float4*>(&sF[rr * 68 + c]) = v;
                }
            }
            __syncthreads();
        }

#pragma unroll
        for (int i = 0; i < 4; i++) {
            int r = a + 16 * i;
            if (sIdx[r] >= 0) {
#pragma unroll 8
                for (int m = 0; m < 64; m++) {
                    float av = sF[r * 68 + m];
                    float4 w = *reinterpret_cast<const float4*>(&sW[m * 64 + 4 * b]);
                    acc[i].x += av * w.x; acc[i].y += av * w.y;
                    acc[i].z += av * w.z; acc[i].w += av * w.w;
                }
            }
        }
    }

    float ls[4] = {0.f, 0.f, 0.f, 0.f}, ls2[4] = {0.f, 0.f, 0.f, 0.f};
#pragma unroll
    for (int i = 0; i < 4; i++) {
        int gr = row0 + a + 16 * i;
        if (gr < N) {
            *reinterpret_cast<float4*>(&out[(size_t)gr * 64 + 4 * b]) = acc[i];
            if (outpart) {
                float v[4] = { acc[i].x, acc[i].y, acc[i].z, acc[i].w };
#pragma unroll
                for (int j = 0; j < 4; j++) { ls[j] += v[j]; ls2[j] += v[j] * v[j]; }
            }
        }
    }
    if (outpart) {
        __syncthreads();
#pragma unroll
        for (int j = 0; j < 4; j++) { sred[0][a][4 * b + j] = ls[j]; sred[1][a][4 * b + j] = ls2[j]; }
        __syncthreads();
        if (t < 64) {
            float s = 0.f, s2 = 0.f;
#pragma unroll
            for (int aa = 0; aa < 16; aa++) { s += sred[0][aa][t]; s2 += sred[1][aa][t]; }
            outpart[blockIdx.x * 128 + t] = s;
            outpart[blockIdx.x * 128 + 64 + t] = s2;
        }
    }
}

// ---------------------------------------------------------------------------
// bf16 3x tensor-core flash attention (champion R10 version).
// ---------------------------------------------------------------------------
#define FLASH_SMEM_BF (65536 + 16384 + 1024)

__global__ void __launch_bounds__(256, 2) k_flash_bf(
    const __nv_bfloat16* __restrict__ gQh, const __nv_bfloat16* __restrict__ gQl,
    const __nv_bfloat16* __restrict__ gKh, const __nv_bfloat16* __restrict__ gKl,
    const __nv_bfloat16* __restrict__ gVh, const __nv_bfloat16* __restrict__ gVl,
    float* __restrict__ O, int seg_off, int tiles_per_seg, int ksplit,
    float* __restrict__ pO, float* __restrict__ pMS)
{
    extern __shared__ char smc[];
    char* sKV = smc;
    char* sQ  = smc + 65536;
    float* red = (float*)(smc + 65536 + 16384);

    int bx = blockIdx.x;
    int segi = bx / tiles_per_seg;
    int traw = bx - segi * tiles_per_seg;
    int tile = traw / ksplit;
    int si = traw - tile * ksplit;
    int seg = seg_off + segi;
    int q0 = g_seg[seg * 4 + 0], nq = g_seg[seg * 4 + 1];
    int k0 = g_seg[seg * 4 + 2], nk = g_seg[seg * 4 + 3];
    if (tile * 64 >= nq) return;
    int qbase = q0 + tile * 64;
    int nqv = min(64, nq - tile * 64);

    int nkt_tot = (nk + 63) >> 6;
    int per = (nkt_tot + ksplit - 1) / ksplit;
    int kt0 = si * per;
    int kt1 = min(nkt_tot, kt0 + per);
    int nkt = kt1 - kt0;

    int t = threadIdx.x;
    int w = t >> 5, lane = t & 31;
    int qg = w & 3, h = w >> 2;
    int quad = lane >> 2, qi = lane & 3;
    int r0 = qg * 16 + quad, r1 = r0 + 8;

    float oc[32];
#pragma unroll
    for (int i = 0; i < 32; i++) oc[i] = 0.f;
    float rmax0 = -1e30f, rmax1 = -1e30f, rsum0 = 0.f, rsum1 = 0.f;

    unsigned Qh[4][4], Ql[4][4];

    if (nkt > 0) {
        {
#pragma unroll
            for (int j = 0; j < 2; j++) {
                int chunk = t + 256 * j;
                int row = chunk >> 3, jj = chunk & 7;
                cpa16(smu32(sQ + SW(row, jj << 4)),        gQh + (size_t)(qbase + row) * 64 + jj * 8);
                cpa16(smu32(sQ + 8192 + SW(row, jj << 4)), gQl + (size_t)(qbase + row) * 64 + jj * 8);
            }
        }
        CP_COMMIT();
        {
            const __nv_bfloat16* gs[4] = { gKh, gKl, gVh, gVl };
            int kb0 = k0 + kt0 * 64;
#pragma unroll
            for (int a = 0; a < 4; a++)
#pragma unroll
                for (int j = 0; j < 2; j++) {
                    int chunk = t + 256 * j;
                    int row = chunk >> 3, jj = chunk & 7;
                    cpa16(smu32(sKV + a * 8192 + SW(row, jj << 4)),
                          gs[a] + (size_t)(kb0 + row) * 64 + jj * 8);
                }
        }
        CP_COMMIT();
        CP_WAIT1();
        __syncthreads();
        {
            int r = qg * 16 + (lane & 7) + ((lane & 8) ? 8 : 0);
#pragma unroll
            for (int ch = 0; ch < 4; ch++) {
                int cb = ch * 32 + ((lane & 16) ? 16 : 0);
                ldsm4(Qh[ch], smu32(sQ + SW(r, cb)));
                ldsm4(Ql[ch], smu32(sQ + 8192 + SW(r, cb)));
            }
        }

        for (int kt = 0; kt < nkt; kt++) {
            char* sb = sKV + (kt & 1) * 32768;
            __syncthreads();
            if (kt + 1 < nkt) {
                char* nb = sKV + ((kt + 1) & 1) * 32768;
                int kb = k0 + (kt0 + kt + 1) * 64;
                const __nv_bfloat16* gs[4] = { gKh, gKl, gVh, gVl };
#pragma unroll
                for (int a = 0; a < 4; a++)
#pragma unroll
                    for (int j = 0; j < 2; j++) {
                        int chunk = t + 256 * j;
                        int row = chunk >> 3, jj = chunk & 7;
                        cpa16(smu32(nb + a * 8192 + SW(row, jj << 4)),
                              gs[a] + (size_t)(kb + row) * 64 + jj * 8);
                    }
            }
            CP_COMMIT();
            CP_WAIT1();
            __syncthreads();

            int nkv = min(64, nk - (kt0 + kt) * 64);
            char* sKh = sb;
            char* sKl = sb + 8192;
            char* sVh = sb + 16384;
            char* sVl = sb + 24576;

            float c4[4][4];
#pragma unroll
            for (int nt = 0; nt < 4; nt++)
#pragma unroll
                for (int k = 0; k < 4; k++) c4[nt][k] = 0.f;

#pragma unroll
            for (int ch = 0; ch < 4; ch++) {
                unsigned kh[8], kl[8];
                {
                    int r = 32 * h + (lane & 7) + ((lane & 16) ? 8 : 0);
                    int cb = ch * 32 + ((lane & 8) ? 16 : 0);
                    ldsm4(kh,     smu32(sKh + SW(r, cb)));
                    ldsm4(kh + 4, smu32(sKh + SW(r + 16, cb)));
                    ldsm4(kl,     smu32(sKl + SW(r, cb)));
                    ldsm4(kl + 4, smu32(sKl + SW(r + 16, cb)));
                }
#pragma unroll
                for (int nt = 0; nt < 4; nt++) {
                    mma_bf(c4[nt], Qh[ch], &kh[2 * nt]);
                    mma_bf(c4[nt], Qh[ch], &kl[2 * nt]);
                    mma_bf(c4[nt], Ql[ch], &kh[2 * nt]);
                }
            }

            if (nkv < 64) {
#pragma unroll
                for (int nt = 0; nt < 4; nt++) {
                    int colb = 32 * h + 8 * nt + 2 * qi;
#pragma unroll
                    for (int k = 0; k < 4; k++)
                        if (colb + (k & 1) >= nkv) c4[nt][k] = -1e30f;
                }
            }

            float mx0 = -1e30f, mx1 = -1e30f;
#pragma unroll
            for (int nt = 0; nt < 4; nt++) {
                mx0 = fmaxf(mx0, fmaxf(c4[nt][0], c4[nt][1]));
                mx1 = fmaxf(mx1, fmaxf(c4[nt][2], c4[nt][3]));
            }
            mx0 = fmaxf(mx0, __shfl_xor_sync(0xffffffffu, mx0, 1));
            mx0 = fmaxf(mx0, __shfl_xor_sync(0xffffffffu, mx0, 2));
            mx1 = fmaxf(mx1, __shfl_xor_sync(0xffffffffu, mx1, 1));
            mx1 = fmaxf(mx1, __shfl_xor_sync(0xffffffffu, mx1, 2));
            float mnew0 = fmaxf(rmax0, mx0);
            float mnew1 = fmaxf(rmax1, mx1);
            float corr0 = __expf(rmax0 - mnew0);
            float corr1 = __expf(rmax1 - mnew1);
            rmax0 = mnew0; rmax1 = mnew1;

            float ps0 = 0.f, ps1 = 0.f;
#pragma unroll
            for (int nt = 0; nt < 4; nt++) {
                float p0 = __expf(c4[nt][0] - mnew0);
                float p1 = __expf(c4[nt][1] - mnew0);
                float p2 = __expf(c4[nt][2] - mnew1);
                float p3 = __expf(c4[nt][3] - mnew1);
                ps0 += p0 + p1; ps1 += p2 + p3;
                c4[nt][0] = p0; c4[nt][1] = p1; c4[nt][2] = p2; c4[nt][3] = p3;
            }
            ps0 += __shfl_xor_sync(0xffffffffu, ps0, 1);
            ps0 += __shfl_xor_sync(0xffffffffu, ps0, 2);
            ps1 += __shfl_xor_sync(0xffffffffu, ps1, 1);
            ps1 += __shfl_xor_sync(0xffffffffu, ps1, 2);
            rsum0 = rsum0 * corr0 + ps0;
            rsum1 = rsum1 * corr1 + ps1;
#pragma unroll
            for (int nt = 0; nt < 8; nt++) {
                oc[nt * 4 + 0] *= corr0; oc[nt * 4 + 1] *= corr0;
                oc[nt * 4 + 2] *= corr1; oc[nt * 4 + 3] *= corr1;
            }

#pragma unroll
            for (int ck = 0; ck < 2; ck++) {
                unsigned pa_h[4], pa_l[4];
                bf_split2(c4[2 * ck][0],     c4[2 * ck][1],     pa_h[0], pa_l[0]);
                bf_split2(c4[2 * ck][2],     c4[2 * ck][3],     pa_h[1], pa_l[1]);
                bf_split2(c4[2 * ck + 1][0], c4[2 * ck + 1][1], pa_h[2], pa_l[2]);
                bf_split2(c4[2 * ck + 1][2], c4[2 * ck + 1][3], pa_h[3], pa_l[3]);
                int key0 = 32 * h + 16 * ck;
#pragma unroll
                for (int cc = 0; cc < 4; cc++) {
                    unsigned vh[4], vl[4];
                    {
                        int r = key0 + (lane & 7) + ((lane & 8) ? 8 : 0);
                        int cb = cc * 32 + ((lane & 16) ? 16 : 0);
                        ldsm4t(vh, smu32(sVh + SW(r, cb)));
                        ldsm4t(vl, smu32(sVl + SW(r, cb)));
                    }
                    mma_bf(&oc[(2 * cc) * 4], pa_h, &vh[0]);
                    mma_bf(&oc[(2 * cc) * 4], pa_h, &vl[0]);
                    mma_bf(&oc[(2 * cc) * 4], pa_l, &vh[0]);
                    mma_bf(&oc[(2 * cc + 1) * 4], pa_h, &vh[2]);
                    mma_bf(&oc[(2 * cc + 1) * 4], pa_h, &vl[2]);
                    mma_bf(&oc[(2 * cc + 1) * 4], pa_l, &vh[2]);
                }
            }
        }
    }

    if (qi == 0) {
        red[h * 64 + r0] = rmax0;       red[h * 64 + r1] = rmax1;
        red[128 + h * 64 + r0] = rsum0; red[128 + h * 64 + r1] = rsum1;
    }
    __syncthreads();

    float m0a = red[r0], m1a = red[64 + r0];
    float mma_ = fmaxf(m0a, m1a);
    float fh_a = __expf(((h == 0) ? m0a : m1a) - mma_);
    float stot_a = red[128 + r0] * __expf(m0a - mma_) + red[192 + r0] * __expf(m1a - mma_);
    float m0b = red[r1], m1b = red[64 + r1];
    float mmb_ = fmaxf(m0b, m1b);
    float fh_b = __expf(((h == 0) ? m0b : m1b) - mmb_);
    float stot_b = red[128 + r1] * __expf(m0b - mmb_) + red[192 + r1] * __expf(m1b - mmb_);

    float* sO = (float*)sQ;
    if (h == 1) {
#pragma unroll
        for (int nt = 0; nt < 8; nt++) {
            int colb = 8 * nt + 2 * qi;
            sO[r0 * 64 + colb]     = oc[nt * 4 + 0] * fh_a;
            sO[r0 * 64 + colb + 1] = oc[nt * 4 + 1] * fh_a;
            sO[r1 * 64 + colb]     = oc[nt * 4 + 2] * fh_b;
            sO[r1 * 64 + colb + 1] = oc[nt * 4 + 3] * fh_b;
        }
    }
    __syncthreads();
    if (h == 0) {
        if (ksplit == 1) {
            float inva = fh_a / stot_a, invb = fh_b / stot_b;
            float ja = 1.f / stot_a, jb = 1.f / stot_b;
#pragma unroll
            for (int nt = 0; nt < 8; nt++) {
                int colb = 8 * nt + 2 * qi;
                if (r0 < nqv) {
                    O[(size_t)(qbase + r0) * 64 + colb]     = oc[nt * 4 + 0] * inva + sO[r0 * 64 + colb] * ja;
                    O[(size_t)(qbase + r0) * 64 + colb + 1] = oc[nt * 4 + 1] * inva + sO[r0 * 64 + colb + 1] * ja;
                }
                if (r1 < nqv) {
                    O[(size_t)(qbase + r1) * 64 + colb]     = oc[nt * 4 + 2] * invb + sO[r1 * 64 + colb] * jb;
                    O[(size_t)(qbase + r1) * 64 + colb + 1] = oc[nt * 4 + 3] * invb + sO[r1 * 64 + colb + 1] * jb;
                }
            }
        } else {
            float* pOo = pO + (size_t)si * CELLS;
            float* pM  = pMS + (size_t)si * 2 * NDMAX;
#pragma unroll
            for (int nt = 0; nt < 8; nt++) {
                int colb = 8 * nt + 2 * qi;
                if (r0 < nqv) {
                    pOo[(size_t)(qbase + r0) * 64 + colb]     = oc[nt * 4 + 0] * fh_a + sO[r0 * 64 + colb];
                    pOo[(size_t)(qbase + r0) * 64 + colb + 1] = oc[nt * 4 + 1] * fh_a + sO[r0 * 64 + colb + 1];
                }
                if (r1 < nqv) {
                    pOo[(size_t)(qbase + r1) * 64 + colb]     = oc[nt * 4 + 2] * fh_b + sO[r1 * 64 + colb];
                    pOo[(size_t)(qbase + r1) * 64 + colb + 1] = oc[nt * 4 + 3] * fh_b + sO[r1 * 64 + colb + 1];
                }
            }
            if (qi == 0) {
                if (r0 < nqv) { pM[(qbase + r0) * 2] = mma_; pM[(qbase + r0) * 2 + 1] = stot_a; }
                if (r1 < nqv) { pM[(qbase + r1) * 2] = mmb_; pM[(qbase + r1) * 2 + 1] = stot_b; }
            }
        }
    }
}

// ---------------------------------------------------------------------------
// BN kernels
// ---------------------------------------------------------------------------
__global__ void k_bnstats_add(const float* __restrict__ X, const float* __restrict__ Y,
                              float* __restrict__ S, int N, float* __restrict__ part)
{
    __shared__ float sh[2][4][64];
    int c = threadIdx.x & 63, rg = threadIdx.x >> 6;
    float s = 0.f, s2 = 0.f;
    for (int r = blockIdx.x * 4 + rg; r < N; r += 256) {
        float v = X[r * 64 + c] + Y[r * 64 + c];
        S[r * 64 + c] = v;
        s += v; s2 += v * v;
    }
    sh[0][rg][c] = s; sh[1][rg][c] = s2;
    __syncthreads();
    if (threadIdx.x < 64) {
        float ts = sh[0][0][c] + sh[0][1][c] + sh[0][2][c] + sh[0][3][c];
        float t2 = sh[1][0][c] + sh[1][1][c] + sh[1][2][c] + sh[1][3][c];
        part[blockIdx.x * 128 + c] = ts;
        part[blockIdx.x * 128 + 64 + c] = t2;
    }
}

__global__ void __launch_bounds__(256) k_bnapply_stats(
    const float* __restrict__ X, const float* __restrict__ Res,
    const float* __restrict__ gamma, const float* __restrict__ beta,
    const float* __restrict__ sp, int snb,
    float* __restrict__ Out, int N, float* __restrict__ outpart)
{
    __shared__ float sh[2][4][64];
    __shared__ float sa[64], sb[64];
    int c = threadIdx.x & 63, rg = threadIdx.x >> 6;
    int row0 = blockIdx.x * 64;
    if (threadIdx.x < 64) bn_coeff(sp, snb, N, c, gamma[c], beta[c], sa[c], sb[c]);
    __syncthreads();
    float A = sa[c], Bc = sb[c];
    float s = 0.f, s2 = 0.f;
#pragma unroll
    for (int i = 0; i < 16; i++) {
        int r = row0 + rg + 4 * i;
        if (r < N) {
            float y = X[r * 64 + c] * A + Bc + Res[r * 64 + c];
            Out[r * 64 + c] = y;
            s += y; s2 += y * y;
        }
    }
    sh[0][rg][c] = s; sh[1][rg][c] = s2;
    __syncthreads();
    if (threadIdx.x < 64) {
        float ts = sh[0][0][c] + sh[0][1][c] + sh[0][2][c] + sh[0][3][c];
        float t2 = sh[1][0][c] + sh[1][1][c] + sh[1][2][c] + sh[1][3][c];
        outpart[blockIdx.x * 128 + c] = ts;
        outpart[blockIdx.x * 128 + 64 + c] = t2;
    }
}

__global__ void __launch_bounds__(256) k_bnapply_fin(
    const float* __restrict__ X,
    const float* __restrict__ gamma, const float* __restrict__ beta,
    const float* __restrict__ sp, int snb,
    float* __restrict__ Out, int N)
{
    __shared__ float sa[64], sb[64];
    int c = threadIdx.x & 63, rg = threadIdx.x >> 6;
    int row0 = blockIdx.x * 64;
    if (threadIdx.x < 64) bn_coeff(sp, snb, N, c, gamma[c], beta[c], sa[c], sb[c]);
    __syncthreads();
    float A = sa[c], Bc = sb[c];
#pragma unroll
    for (int i = 0; i < 16; i++) {
        int r = row0 + rg + 4 * i;
        if (r < N) Out[r * 64 + c] = fmaxf(X[r * 64 + c] * A + Bc, 0.f);
    }
}

// ---------------------------------------------------------------------------
extern "C" void kernel_launch(void* const* d_in, const int* in_sizes, int n_in,
                              void* d_out, int out_size)
{
    const float* xdec  = (const float*)d_in[0];
    const float* xenc  = (const float*)d_in[1];
    const float* Wp1   = (const float*)d_in[2];
    const float* Wq    = (const float*)d_in[3];
    const float* Wk    = (const float*)d_in[4];
    const float* Wv    = (const float*)d_in[5];
    const float* Wt    = (const float*)d_in[6];
    const float* Wq1   = (const float*)d_in[7];
    const float* Wk1   = (const float*)d_in[8];
    const float* Wv1   = (const float*)d_in[9];
    const float* Wdown = (const float*)d_in[10];
    const float* W3t   = (const float*)d_in[11];
    const float* W3a   = (const float*)d_in[12];
    const float* W3b   = (const float*)d_in[13];
    const float* gam   = (const float*)d_in[14];
    const float* bet   = (const float*)d_in[15];
    const int* nbr     = (const int*)d_in[16];
    const int* kv_nbr  = (const int*)d_in[17];
    const int* pad_idx = (const int*)d_in[18];

    int nd = in_sizes[0] / 64;
    int ne = in_sizes[1] / 64;
    int lq = in_sizes[18] / NBATCH;
    float* out = (float*)d_out;

    float* base = nullptr;   cudaGetSymbolAddress((void**)&base, g_buf);
    float* pob = nullptr;    cudaGetSymbolAddress((void**)&pob, g_po);
    float* pmsb = nullptr;   cudaGetSymbolAddress((void**)&pmsb, g_pms);
    float* partb = nullptr;  cudaGetSymbolAddress((void**)&partb, g_part);
    __nv_bfloat16* bfb = nullptr; cudaGetSymbolAddress((void**)&bfb, g_bf);
    __nv_bfloat16* wtb = nullptr; cudaGetSymbolAddress((void**)&wtb, g_wtb);

    float* B[15];
    for (int i = 0; i < 15; i++) B[i] = base + (size_t)i * CELLS;
    __nv_bfloat16* BF[6];
    for (int i = 0; i < 6; i++) BF[i] = bfb + (size_t)i * PADCELLS;
    __nv_bfloat16* WT[8];
    for (int i = 0; i < 8; i++) WT[i] = wtb + (size_t)i * 8192;
    float* partA = partb;
    float* partB = partb + 256 * 128;

    cudaFuncSetAttribute(k_flash_bf, cudaFuncAttributeMaxDynamicSharedMemorySize, FLASH_SMEM_BF);
    cudaFuncSetAttribute(k_gconv, cudaFuncAttributeMaxDynamicSharedMemorySize, GC_SMEM);

    dim3 thr(256);
    int gbd = (nd + 63) / 64;
    int gbe = (ne + 63) / 64;
    int gx = gbd > gbe ? gbd : gbe;

    // ---- init ----
    k_init<<<9, thr>>>(Wp1, Wq, Wk, Wv, Wt, Wq1, Wk1, Wv1, pad_idx, nd, ne, lq);

    // ---- Stage 1 ----
    {
        TJobs JJ = {};
        JJ.j[0].A = xdec; JJ.j[0].Wbf = WT[0]; JJ.j[0].C = B[0]; JJ.j[0].N = nd; JJ.j[0].mode = 0;
        JJ.j[1].A = xdec; JJ.j[1].Wbf = WT[1]; JJ.j[1].hi = BF[0]; JJ.j[1].lo = BF[1]; JJ.j[1].N = nd; JJ.j[1].mode = 0;
        JJ.j[2].A = xenc; JJ.j[2].Wbf = WT[2]; JJ.j[2].hi = BF[2]; JJ.j[2].lo = BF[3]; JJ.j[2].N = ne; JJ.j[2].mode = 0;
        JJ.j[3].A = xenc; JJ.j[3].Wbf = WT[3]; JJ.j[3].hi = BF[4]; JJ.j[3].lo = BF[5]; JJ.j[3].N = ne; JJ.j[3].mode = 0;
        k_tgemm<<<dim3(gx, 4), thr>>>(JJ);
    }
    k_flash_bf<<<gbd * KS, thr, FLASH_SMEM_BF>>>(BF[0], BF[1], BF[2], BF[3], BF[4], BF[5],
                                                 B[4], 0, gbd * KS, KS, pob, pmsb);
    {   // xr = merge(splitK) @ Wt (+stats A)
        TJobs JJ = {};
        JJ.j[0].pO = pob; JJ.j[0].pMS = pmsb; JJ.j[0].Wbf = WT[4];
        JJ.j[0].C = B[5]; JJ.j[0].part = partA; JJ.j[0].N = nd; JJ.j[0].mode = 3;
        k_tgemm<<<dim3(gbd, 1), thr>>>(JJ);
    }
    {   // xd = bn(xr)+xd0 -> B6 ; q1 = xd@Wq1 -> B7 + BF0/1
        TJobs JJ = {};
        JJ.j[0].A = B[5]; JJ.j[0].Res = B[0]; JJ.j[0].bg = gam + 0; JJ.j[0].bb = bet + 0;
        JJ.j[0].sp = partA; JJ.j[0].snb = gbd; JJ.j[0].Aout = B[6];
        JJ.j[0].Wbf = WT[5]; JJ.j[0].C = B[7]; JJ.j[0].hi = BF[0]; JJ.j[0].lo = BF[1];
        JJ.j[0].N = nd; JJ.j[0].mode = 2;
        k_tgemm<<<dim3(gbd, 1), thr>>>(JJ);
    }

    // ---- Stage 2 ----
    k_gconv<<<gbd, thr, GC_SMEM>>>(B[7], kv_nbr, 8, Wdown, B[8], nd,
                                   partA, nullptr, 0, nullptr, nullptr);
    {   // k1, v1 = bn(kv) @ {Wk1, Wv1}
        TJobs JJ = {};
        JJ.j[0].A = B[8]; JJ.j[0].Wbf = WT[6]; JJ.j[0].hi = BF[2]; JJ.j[0].lo = BF[3];
        JJ.j[0].bg = gam + 64; JJ.j[0].bb = bet + 64; JJ.j[0].sp = partA; JJ.j[0].snb = gbd;
        JJ.j[0].N = nd; JJ.j[0].mode = 1;
        JJ.j[1] = JJ.j[0];
        JJ.j[1].Wbf = WT[7]; JJ.j[1].hi = BF[4]; JJ.j[1].lo = BF[5];
        k_tgemm<<<dim3(gbd, 2), thr>>>(JJ);
    }
    int tps = (lq + 63) / 64;
    k_flash_bf<<<NBATCH * tps, thr, FLASH_SMEM_BF>>>(BF[0], BF[1], BF[2], BF[3], BF[4], BF[5],
                                                     B[12], 1, tps, 1, nullptr, nullptr);
    k_gconv<<<gbd, thr, GC_SMEM>>>(B[12], nbr, 27, W3t, B[13], nd,
                                   partA, nullptr, 0, nullptr, nullptr);
    k_bnapply_stats<<<gbd, thr>>>(B[13], B[6], gam + 128, bet + 128, partA, gbd,
                                  B[14], nd, partB);

    // ---- Res block ----
    k_gconv<<<gbd, thr, GC_SMEM>>>(B[14], nbr, 27, W3a, B[1], nd,
                                   partA, partB, gbd, gam + 192, bet + 192);
    k_gconv<<<gbd, thr, GC_SMEM>>>(B[1], nbr, 27, W3b, B[3], nd,
                                   nullptr, partA, gbd, gam + 256, bet + 256);
    k_bnstats_add<<<64, thr>>>(B[14], B[3], B[4], nd, partA);
    k_bnapply_fin<<<gbd, thr>>>(B[4], gam + 320, bet + 320, partA, 64, out, nd);
}